// round 8
// baseline (speedup 1.0000x reference)
#include <cuda_runtime.h>
#include <cuda_bf16.h>
#include <cstdint>

// ---------------- problem constants ----------------
#define TKN   8192          // T = B*S
#define BATCH 8
#define SEQ   1024
#define HID   2560
#define NH    32            // q heads
#define NKV   32            // kv heads
#define HD    80            // head dim
#define ROT   40
#define RHALF 20
#define QKVD  7680          // (32+64)*80
#define ATT_SCALE 0.08838834764831843f  // 1/sqrt(128)

// ---------------- scratch (device globals: allocation-free) ----------------
__device__ float g_qkv[(size_t)TKN * QKVD];            // 251 MB fp32
__device__ float g_attn[(size_t)TKN * HID];            // 80 MB fp32
__device__ __nv_bfloat16 g_ah[(size_t)TKN * HID];      // A hi (hidden, then attn)
__device__ __nv_bfloat16 g_al[(size_t)TKN * HID];      // A lo
__device__ __nv_bfloat16 g_wh[(size_t)QKVD * HID];     // W hi (w_qkv, then w_dense)
__device__ __nv_bfloat16 g_wl[(size_t)QKVD * HID];     // W lo

// ======================================================================
// helpers
// ======================================================================
__device__ __forceinline__ uint32_t smem_u32(const void* p) {
    uint32_t a;
    asm("{ .reg .u64 t; cvta.to.shared.u64 t, %1; cvt.u32.u64 %0, t; }"
        : "=r"(a) : "l"(p));
    return a;
}

#define CP16(dst, src) \
    asm volatile("cp.async.cg.shared.global [%0], [%1], 16;" \
                 :: "r"(dst), "l"(src))
#define CP_COMMIT() asm volatile("cp.async.commit_group;" ::: "memory")
#define CP_WAIT1()  asm volatile("cp.async.wait_group 1;" ::: "memory")

#define LDSM4(r, addr) \
    asm volatile("ldmatrix.sync.aligned.m8n8.x4.shared.b16 {%0,%1,%2,%3}, [%4];" \
                 : "=r"((r)[0]), "=r"((r)[1]), "=r"((r)[2]), "=r"((r)[3]) \
                 : "r"(addr))

#define MMA_BF16(c, a, b0, b1) \
    asm volatile("mma.sync.aligned.m16n8k16.row.col.f32.bf16.bf16.f32 " \
                 "{%0,%1,%2,%3}, {%4,%5,%6,%7}, {%8,%9}, {%0,%1,%2,%3};" \
                 : "+f"((c)[0]), "+f"((c)[1]), "+f"((c)[2]), "+f"((c)[3]) \
                 : "r"((a)[0]), "r"((a)[1]), "r"((a)[2]), "r"((a)[3]), \
                   "r"(b0), "r"(b1))

// ======================================================================
// split fp32 -> bf16 hi (rn) + bf16 lo (rn of residual)
// ======================================================================
__global__ __launch_bounds__(256) void split_kernel(
    const float4* __restrict__ src, uint2* __restrict__ hi,
    uint2* __restrict__ lo, int n4)
{
    int i = blockIdx.x * blockDim.x + threadIdx.x;
    if (i >= n4) return;
    float4 v = src[i];
    __nv_bfloat162 h0, h1, l0, l1;
    h0.x = __float2bfloat16(v.x); h0.y = __float2bfloat16(v.y);
    h1.x = __float2bfloat16(v.z); h1.y = __float2bfloat16(v.w);
    l0.x = __float2bfloat16(v.x - __bfloat162float(h0.x));
    l0.y = __float2bfloat16(v.y - __bfloat162float(h0.y));
    l1.x = __float2bfloat16(v.z - __bfloat162float(h1.x));
    l1.y = __float2bfloat16(v.w - __bfloat162float(h1.y));
    hi[i] = make_uint2(*reinterpret_cast<uint32_t*>(&h0),
                       *reinterpret_cast<uint32_t*>(&h1));
    lo[i] = make_uint2(*reinterpret_cast<uint32_t*>(&l0),
                       *reinterpret_cast<uint32_t*>(&l1));
}

// ======================================================================
// bf16 split GEMM: C[M,N] = A[M,K] @ B[N,K]^T + bias[N]
// A = Ah + Al, B = Bh + Bl; C ~= Ah Bh + Ah Bl + Al Bh (fp32 accum)
// 128x128 tile, BK=32 (bf16), 3-stage cp.async pipeline, 8 warps (2M x 4N).
// ======================================================================
#define BM 128
#define BN 128
#define BKB 32
#define STAGES 3
#define ROWB 80                  // padded smem row bytes (40 bf16)
#define BUFB (128 * ROWB)        // 10240 B per operand buffer
#define STAGEB (4 * BUFB)        // 40960 B per stage
#define GSMEM (STAGES * STAGEB)  // 122880 B

__global__ __launch_bounds__(256, 1) void gemm_bf16_split(
    const __nv_bfloat16* __restrict__ Ah, const __nv_bfloat16* __restrict__ Al,
    const __nv_bfloat16* __restrict__ Bh, const __nv_bfloat16* __restrict__ Bl,
    const float* __restrict__ bias, float* __restrict__ C,
    int M, int N, int K)
{
    extern __shared__ char smraw[];
    const uint32_t s0 = smem_u32(smraw);

    const int tid = threadIdx.x;
    const int lane = tid & 31;
    const int wid = tid >> 5;
    const int wm = wid & 1;       // 2 warps in M (64 rows each)
    const int wn = wid >> 1;      // 4 warps in N (32 cols each)

    const int bm0 = blockIdx.y * BM;
    const int bn0 = blockIdx.x * BN;

    const __nv_bfloat16* Ahb = Ah + (size_t)bm0 * K;
    const __nv_bfloat16* Alb = Al + (size_t)bm0 * K;
    const __nv_bfloat16* Bhb = Bh + (size_t)bn0 * K;
    const __nv_bfloat16* Blb = Bl + (size_t)bn0 * K;

    float acc[4][4][4];
#pragma unroll
    for (int i = 0; i < 4; i++)
#pragma unroll
        for (int j = 0; j < 4; j++)
#pragma unroll
            for (int q = 0; q < 4; q++) acc[i][j][q] = 0.f;

    const int nch = K / BKB;   // 80

    // ---- prologue: issue stages 0..STAGES-2 ----
#pragma unroll
    for (int s = 0; s < STAGES - 1; ++s) {
        const uint32_t sb = s0 + s * STAGEB;
        const int k0 = s * BKB;
#pragma unroll
        for (int it = 0; it < 2; ++it) {
            int idx = tid + it * 256;
            int r = idx >> 2, ch = idx & 3;
            uint32_t doff = (uint32_t)(r * ROWB + ch * 16);
            size_t roff = (size_t)r * K + k0 + ch * 8;
            CP16(sb + 0 * BUFB + doff, Ahb + roff);
            CP16(sb + 1 * BUFB + doff, Alb + roff);
            CP16(sb + 2 * BUFB + doff, Bhb + roff);
            CP16(sb + 3 * BUFB + doff, Blb + roff);
        }
        CP_COMMIT();
    }

    int stg = 0;
    for (int c = 0; c < nch; ++c) {
        CP_WAIT1();
        __syncthreads();

        // issue chunk c+STAGES-1 into the stage we just freed
        const int nc = c + STAGES - 1;
        if (nc < nch) {
            const int ns = (stg + STAGES - 1) % STAGES;
            const uint32_t sb = s0 + ns * STAGEB;
            const int k0 = nc * BKB;
#pragma unroll
            for (int it = 0; it < 2; ++it) {
                int idx = tid + it * 256;
                int r = idx >> 2, ch = idx & 3;
                uint32_t doff = (uint32_t)(r * ROWB + ch * 16);
                size_t roff = (size_t)r * K + k0 + ch * 8;
                CP16(sb + 0 * BUFB + doff, Ahb + roff);
                CP16(sb + 1 * BUFB + doff, Alb + roff);
                CP16(sb + 2 * BUFB + doff, Bhb + roff);
                CP16(sb + 3 * BUFB + doff, Blb + roff);
            }
        }
        CP_COMMIT();

        // ---- compute current stage ----
        const uint32_t aH = s0 + stg * STAGEB;
        const uint32_t bH = aH + 2 * BUFB;
#pragma unroll
        for (int ks = 0; ks < 2; ++ks) {
            const int kc = ks * 16;
            uint32_t ah[4][4], al[4][4];
            uint32_t bh[4][2], bl[4][2];
#pragma unroll
            for (int i = 0; i < 4; ++i) {
                uint32_t addr = aH + (uint32_t)((wm * 64 + i * 16 + (lane & 15)) * ROWB
                                 + kc * 2 + (lane >> 4) * 16);
                LDSM4(ah[i], addr);
                LDSM4(al[i], addr + BUFB);
            }
#pragma unroll
            for (int jj = 0; jj < 2; ++jj) {
                uint32_t addr = bH + (uint32_t)((wn * 32 + jj * 16 + (lane & 15)) * ROWB
                                 + kc * 2 + (lane >> 4) * 16);
                uint32_t t[4];
                LDSM4(t, addr);
                bh[2 * jj][0] = t[0]; bh[2 * jj][1] = t[2];
                bh[2 * jj + 1][0] = t[1]; bh[2 * jj + 1][1] = t[3];
                LDSM4(t, addr + BUFB);
                bl[2 * jj][0] = t[0]; bl[2 * jj][1] = t[2];
                bl[2 * jj + 1][0] = t[1]; bl[2 * jj + 1][1] = t[3];
            }
#pragma unroll
            for (int i = 0; i < 4; ++i) {
#pragma unroll
                for (int j = 0; j < 4; ++j) {
                    MMA_BF16(acc[i][j], ah[i], bh[j][0], bh[j][1]);
                    MMA_BF16(acc[i][j], ah[i], bl[j][0], bl[j][1]);
                    MMA_BF16(acc[i][j], al[i], bh[j][0], bh[j][1]);
                }
            }
        }
        stg = (stg + 1 == STAGES) ? 0 : stg + 1;
    }

    // ---- epilogue: bias + store fp32 ----
#pragma unroll
    for (int i = 0; i < 4; ++i) {
        const int row = bm0 + wm * 64 + i * 16 + (lane >> 2);
#pragma unroll
        for (int j = 0; j < 4; ++j) {
            const int col = bn0 + wn * 32 + j * 8 + (lane & 3) * 2;
            const float b0 = bias[col], b1 = bias[col + 1];
            float2 v0 = make_float2(acc[i][j][0] + b0, acc[i][j][1] + b1);
            float2 v1 = make_float2(acc[i][j][2] + b0, acc[i][j][3] + b1);
            *reinterpret_cast<float2*>(C + (size_t)row * N + col) = v0;
            *reinterpret_cast<float2*>(C + (size_t)(row + 8) * N + col) = v1;
        }
    }
}

// ======================================================================
// Partial RoPE on q (cols [0,2560)) and k (cols [2560,5120)) of g_qkv.
// ======================================================================
__global__ __launch_bounds__(256) void rope_kernel(
    float* __restrict__ qkv, const float* __restrict__ cosb,
    const float* __restrict__ sinb)
{
    const int t = blockIdx.x;
    float* row = qkv + (size_t)t * QKVD;
    for (int w = threadIdx.x; w < 64 * RHALF; w += blockDim.x) {
        int head = w / RHALF;
        int i    = w % RHALF;
        int base = head * HD;
        float c = cosb[t * RHALF + i];
        float s = sinb[t * RHALF + i];
        float x1 = row[base + i];
        float x2 = row[base + RHALF + i];
        row[base + i]          = x1 * c - x2 * s;
        row[base + RHALF + i]  = x2 * c + x1 * s;
    }
}

// ======================================================================
// Flash attention (fp32, causal) — unchanged from R1 (passing, ~1.6ms).
// ======================================================================
#define QT 64
#define KT 64
#define QKP 68
#define VP  84

struct FlashSmem {
    float Qs[HD][QKP];
    float Ks[HD][QKP];
    float Vs[KT][VP];
    float Ss[QT][KT + 1];
};

__global__ __launch_bounds__(256) void flash_kernel(
    const float* __restrict__ qkv, float* __restrict__ attn_out)
{
    extern __shared__ char smem_raw[];
    FlashSmem& sm = *reinterpret_cast<FlashSmem*>(smem_raw);

    const int qt = blockIdx.x;
    const int h  = blockIdx.y;
    const int b  = blockIdx.z;
    const int tid = threadIdx.x;

    const int tc = tid & 15;
    const int tr = tid >> 4;
    const int orow = tid >> 2;
    const int og   = tid & 3;

    const int tq0 = b * SEQ + qt * QT;

    for (int idx = tid; idx < QT * (HD / 4); idx += 256) {
        int r  = idx / (HD / 4);
        int d4 = (idx % (HD / 4)) * 4;
        float4 qv = *reinterpret_cast<const float4*>(
            qkv + (size_t)(tq0 + r) * QKVD + h * HD + d4);
        sm.Qs[d4 + 0][r] = qv.x; sm.Qs[d4 + 1][r] = qv.y;
        sm.Qs[d4 + 2][r] = qv.z; sm.Qs[d4 + 3][r] = qv.w;
    }

    float m = -1e30f;
    float lsum = 0.f;
    float O[20];
#pragma unroll
    for (int d = 0; d < 20; d++) O[d] = 0.f;

    for (int kt = 0; kt <= qt; kt++) {
        const int tk0 = b * SEQ + kt * KT;

        for (int idx = tid; idx < KT * (HD / 4); idx += 256) {
            int r  = idx / (HD / 4);
            int d4 = (idx % (HD / 4)) * 4;
            const float* base = qkv + (size_t)(tk0 + r) * QKVD + h * HD + d4;
            float4 kv = *reinterpret_cast<const float4*>(base + HID);
            sm.Ks[d4 + 0][r] = kv.x; sm.Ks[d4 + 1][r] = kv.y;
            sm.Ks[d4 + 2][r] = kv.z; sm.Ks[d4 + 3][r] = kv.w;
            float4 vv = *reinterpret_cast<const float4*>(base + 2 * HID);
            *reinterpret_cast<float4*>(&sm.Vs[r][d4]) = vv;
        }
        __syncthreads();

        {
            float acc[4][4];
#pragma unroll
            for (int i = 0; i < 4; i++)
#pragma unroll
                for (int j = 0; j < 4; j++) acc[i][j] = 0.f;

            for (int d = 0; d < HD; d++) {
                float4 q4 = *reinterpret_cast<const float4*>(&sm.Qs[d][tr * 4]);
                float4 k4 = *reinterpret_cast<const float4*>(&sm.Ks[d][tc * 4]);
                float qa[4] = {q4.x, q4.y, q4.z, q4.w};
                float ka[4] = {k4.x, k4.y, k4.z, k4.w};
#pragma unroll
                for (int i = 0; i < 4; i++)
#pragma unroll
                    for (int j = 0; j < 4; j++)
                        acc[i][j] = fmaf(qa[i], ka[j], acc[i][j]);
            }
#pragma unroll
            for (int i = 0; i < 4; i++)
#pragma unroll
                for (int j = 0; j < 4; j++)
                    sm.Ss[tr * 4 + i][tc * 4 + j] = acc[i][j] * ATT_SCALE;
        }
        __syncthreads();

        {
            const int c0 = og * 16;
            const bool diag = (kt == qt);
            float sv[16];
            float tmax = -1e30f;
#pragma unroll
            for (int i = 0; i < 16; i++) {
                int c = c0 + i;
                float s = sm.Ss[orow][c];
                if (diag && c > orow) s = -1e30f;
                sv[i] = s;
                tmax = fmaxf(tmax, s);
            }
            tmax = fmaxf(tmax, __shfl_xor_sync(0xffffffffu, tmax, 1));
            tmax = fmaxf(tmax, __shfl_xor_sync(0xffffffffu, tmax, 2));

            float newm = fmaxf(m, tmax);
            float alpha = __expf(m - newm);
            float lpart = 0.f;
#pragma unroll
            for (int i = 0; i < 16; i++) {
                float p = __expf(sv[i] - newm);
                sm.Ss[orow][c0 + i] = p;
                lpart += p;
            }
            lsum = lsum * alpha + lpart;
            m = newm;
#pragma unroll
            for (int d = 0; d < 20; d++) O[d] *= alpha;
        }
        __syncwarp();

        {
            const int d0 = og * 20;
            for (int j = 0; j < KT; j++) {
                float p = sm.Ss[orow][j];
                const float* vrow = &sm.Vs[j][d0];
#pragma unroll
                for (int c = 0; c < 5; c++) {
                    float4 v4 = *reinterpret_cast<const float4*>(vrow + c * 4);
                    O[c * 4 + 0] = fmaf(p, v4.x, O[c * 4 + 0]);
                    O[c * 4 + 1] = fmaf(p, v4.y, O[c * 4 + 1]);
                    O[c * 4 + 2] = fmaf(p, v4.z, O[c * 4 + 2]);
                    O[c * 4 + 3] = fmaf(p, v4.w, O[c * 4 + 3]);
                }
            }
        }
        __syncthreads();
    }

    float ltot = lsum;
    ltot += __shfl_xor_sync(0xffffffffu, ltot, 1);
    ltot += __shfl_xor_sync(0xffffffffu, ltot, 2);
    float inv = 1.f / ltot;

    const int t = tq0 + orow;
    float* dst = attn_out + (size_t)t * HID + h * HD + og * 20;
#pragma unroll
    for (int d = 0; d < 20; d++) dst[d] = O[d] * inv;
}

// ======================================================================
// launch
// ======================================================================
extern "C" void kernel_launch(void* const* d_in, const int* in_sizes, int n_in,
                              void* d_out, int out_size)
{
    const float* hidden  = (const float*)d_in[0];
    const float* cosb    = (const float*)d_in[1];
    const float* sinb    = (const float*)d_in[2];
    const float* w_qkv   = (const float*)d_in[3];
    const float* b_qkv   = (const float*)d_in[4];
    const float* w_dense = (const float*)d_in[5];
    const float* b_dense = (const float*)d_in[6];
    float* out = (float*)d_out;

    float *qkv = nullptr, *attn = nullptr;
    __nv_bfloat16 *ah = nullptr, *al = nullptr, *wh = nullptr, *wl = nullptr;
    cudaGetSymbolAddress((void**)&qkv, g_qkv);
    cudaGetSymbolAddress((void**)&attn, g_attn);
    cudaGetSymbolAddress((void**)&ah, g_ah);
    cudaGetSymbolAddress((void**)&al, g_al);
    cudaGetSymbolAddress((void**)&wh, g_wh);
    cudaGetSymbolAddress((void**)&wl, g_wl);

    cudaFuncSetAttribute(gemm_bf16_split,
                         cudaFuncAttributeMaxDynamicSharedMemorySize, GSMEM);
    cudaFuncSetAttribute(flash_kernel,
                         cudaFuncAttributeMaxDynamicSharedMemorySize,
                         (int)sizeof(FlashSmem));

    const int nA4 = TKN * HID / 4;      // 5,242,880
    const int nW4 = QKVD * HID / 4;     // 4,915,200
    const int nD4 = HID * HID / 4;      // 1,638,400

    // 1) split hidden + w_qkv to bf16 hi/lo
    split_kernel<<<(nA4 + 255) / 256, 256>>>(
        (const float4*)hidden, (uint2*)ah, (uint2*)al, nA4);
    split_kernel<<<(nW4 + 255) / 256, 256>>>(
        (const float4*)w_qkv, (uint2*)wh, (uint2*)wl, nW4);

    // 2) QKV projection: [8192,2560] @ [7680,2560]^T + b -> [8192,7680]
    gemm_bf16_split<<<dim3(QKVD / BN, TKN / BM), 256, GSMEM>>>(
        ah, al, wh, wl, b_qkv, qkv, TKN, QKVD, HID);

    // 3) partial RoPE in place on q,k
    rope_kernel<<<TKN, 256>>>(qkv, cosb, sinb);

    // 4) causal flash attention -> g_attn [8192,2560]
    flash_kernel<<<dim3(SEQ / QT, NH, BATCH), 256, sizeof(FlashSmem)>>>(qkv, attn);

    // 5) split attn + w_dense
    split_kernel<<<(nA4 + 255) / 256, 256>>>(
        (const float4*)attn, (uint2*)ah, (uint2*)al, nA4);
    split_kernel<<<(nD4 + 255) / 256, 256>>>(
        (const float4*)w_dense, (uint2*)wh, (uint2*)wl, nD4);

    // 6) dense projection: [8192,2560] @ [2560,2560]^T + b -> out
    gemm_bf16_split<<<dim3(HID / BN, TKN / BM), 256, GSMEM>>>(
        ah, al, wh, wl, b_dense, out, TKN, HID, HID);
}

// round 9
// speedup vs baseline: 1.0022x; 1.0022x over previous
#include <cuda_runtime.h>
#include <cuda_bf16.h>
#include <cstdint>

// ---------------- problem constants ----------------
#define TKN   8192          // T = B*S
#define BATCH 8
#define SEQ   1024
#define HID   2560
#define NH    32            // q heads
#define NKV   32            // kv heads
#define HD    80            // head dim
#define ROT   40
#define RHALF 20
#define QKVD  7680          // (32+64)*80
#define ATT_SCALE 0.08838834764831843f  // 1/sqrt(128)

// ---------------- scratch (device globals: allocation-free) ----------------
__device__ float g_qkv[(size_t)TKN * QKVD];            // 251 MB fp32
__device__ float g_attn[(size_t)TKN * HID];            // 80 MB fp32
__device__ __nv_bfloat16 g_ah[(size_t)TKN * HID];      // A hi (hidden, then attn)
__device__ __nv_bfloat16 g_al[(size_t)TKN * HID];      // A lo
__device__ __nv_bfloat16 g_wh[(size_t)QKVD * HID];     // W hi (w_qkv, then w_dense)
__device__ __nv_bfloat16 g_wl[(size_t)QKVD * HID];     // W lo

// ======================================================================
// helpers
// ======================================================================
__device__ __forceinline__ uint32_t smem_u32(const void* p) {
    uint32_t a;
    asm("{ .reg .u64 t; cvta.to.shared.u64 t, %1; cvt.u32.u64 %0, t; }"
        : "=r"(a) : "l"(p));
    return a;
}

#define CP16(dst, src) \
    asm volatile("cp.async.cg.shared.global [%0], [%1], 16;" \
                 :: "r"(dst), "l"(src))
#define CP_COMMIT() asm volatile("cp.async.commit_group;" ::: "memory")
#define CP_WAIT1()  asm volatile("cp.async.wait_group 1;" ::: "memory")

#define LDSM4(r, addr) \
    asm volatile("ldmatrix.sync.aligned.m8n8.x4.shared.b16 {%0,%1,%2,%3}, [%4];" \
                 : "=r"((r)[0]), "=r"((r)[1]), "=r"((r)[2]), "=r"((r)[3]) \
                 : "r"(addr))

#define MMA_BF16(c, a, b0, b1) \
    asm volatile("mma.sync.aligned.m16n8k16.row.col.f32.bf16.bf16.f32 " \
                 "{%0,%1,%2,%3}, {%4,%5,%6,%7}, {%8,%9}, {%0,%1,%2,%3};" \
                 : "+f"((c)[0]), "+f"((c)[1]), "+f"((c)[2]), "+f"((c)[3]) \
                 : "r"((a)[0]), "r"((a)[1]), "r"((a)[2]), "r"((a)[3]), \
                   "r"(b0), "r"(b1))

// ======================================================================
// split fp32 -> bf16 hi (rn) + bf16 lo (rn of residual)
// ======================================================================
__global__ __launch_bounds__(256) void split_kernel(
    const float4* __restrict__ src, uint2* __restrict__ hi,
    uint2* __restrict__ lo, int n4)
{
    int i = blockIdx.x * blockDim.x + threadIdx.x;
    if (i >= n4) return;
    float4 v = src[i];
    __nv_bfloat162 h0, h1, l0, l1;
    h0.x = __float2bfloat16(v.x); h0.y = __float2bfloat16(v.y);
    h1.x = __float2bfloat16(v.z); h1.y = __float2bfloat16(v.w);
    l0.x = __float2bfloat16(v.x - __bfloat162float(h0.x));
    l0.y = __float2bfloat16(v.y - __bfloat162float(h0.y));
    l1.x = __float2bfloat16(v.z - __bfloat162float(h1.x));
    l1.y = __float2bfloat16(v.w - __bfloat162float(h1.y));
    hi[i] = make_uint2(*reinterpret_cast<uint32_t*>(&h0),
                       *reinterpret_cast<uint32_t*>(&h1));
    lo[i] = make_uint2(*reinterpret_cast<uint32_t*>(&l0),
                       *reinterpret_cast<uint32_t*>(&l1));
}

// ======================================================================
// bf16 split GEMM: C[M,N] = A[M,K] @ B[N,K]^T + bias[N]
// A = Ah + Al, B = Bh + Bl; C ~= Ah Bh + Ah Bl + Al Bh (fp32 accum)
// 128x128 tile, BK=32 (bf16), 3-stage cp.async pipeline, 8 warps (2M x 4N).
// ======================================================================
#define BM 128
#define BN 128
#define BKB 32
#define STAGES 3
#define ROWB 80                  // padded smem row bytes (40 bf16)
#define BUFB (128 * ROWB)        // 10240 B per operand buffer
#define STAGEB (4 * BUFB)        // 40960 B per stage
#define GSMEM (STAGES * STAGEB)  // 122880 B

__global__ __launch_bounds__(256, 1) void gemm_bf16_split(
    const __nv_bfloat16* __restrict__ Ah, const __nv_bfloat16* __restrict__ Al,
    const __nv_bfloat16* __restrict__ Bh, const __nv_bfloat16* __restrict__ Bl,
    const float* __restrict__ bias, float* __restrict__ C,
    int M, int N, int K)
{
    extern __shared__ char smraw[];
    const uint32_t s0 = smem_u32(smraw);

    const int tid = threadIdx.x;
    const int lane = tid & 31;
    const int wid = tid >> 5;
    const int wm = wid & 1;       // 2 warps in M (64 rows each)
    const int wn = wid >> 1;      // 4 warps in N (32 cols each)

    const int bm0 = blockIdx.y * BM;
    const int bn0 = blockIdx.x * BN;

    const __nv_bfloat16* Ahb = Ah + (size_t)bm0 * K;
    const __nv_bfloat16* Alb = Al + (size_t)bm0 * K;
    const __nv_bfloat16* Bhb = Bh + (size_t)bn0 * K;
    const __nv_bfloat16* Blb = Bl + (size_t)bn0 * K;

    float acc[4][4][4];
#pragma unroll
    for (int i = 0; i < 4; i++)
#pragma unroll
        for (int j = 0; j < 4; j++)
#pragma unroll
            for (int q = 0; q < 4; q++) acc[i][j][q] = 0.f;

    const int nch = K / BKB;   // 80

    // ---- prologue: issue stages 0..STAGES-2 ----
#pragma unroll
    for (int s = 0; s < STAGES - 1; ++s) {
        const uint32_t sb = s0 + s * STAGEB;
        const int k0 = s * BKB;
#pragma unroll
        for (int it = 0; it < 2; ++it) {
            int idx = tid + it * 256;
            int r = idx >> 2, ch = idx & 3;
            uint32_t doff = (uint32_t)(r * ROWB + ch * 16);
            size_t roff = (size_t)r * K + k0 + ch * 8;
            CP16(sb + 0 * BUFB + doff, Ahb + roff);
            CP16(sb + 1 * BUFB + doff, Alb + roff);
            CP16(sb + 2 * BUFB + doff, Bhb + roff);
            CP16(sb + 3 * BUFB + doff, Blb + roff);
        }
        CP_COMMIT();
    }

    int stg = 0;
    for (int c = 0; c < nch; ++c) {
        CP_WAIT1();
        __syncthreads();

        // issue chunk c+STAGES-1 into the stage we just freed
        const int nc = c + STAGES - 1;
        if (nc < nch) {
            const int ns = (stg + STAGES - 1) % STAGES;
            const uint32_t sb = s0 + ns * STAGEB;
            const int k0 = nc * BKB;
#pragma unroll
            for (int it = 0; it < 2; ++it) {
                int idx = tid + it * 256;
                int r = idx >> 2, ch = idx & 3;
                uint32_t doff = (uint32_t)(r * ROWB + ch * 16);
                size_t roff = (size_t)r * K + k0 + ch * 8;
                CP16(sb + 0 * BUFB + doff, Ahb + roff);
                CP16(sb + 1 * BUFB + doff, Alb + roff);
                CP16(sb + 2 * BUFB + doff, Bhb + roff);
                CP16(sb + 3 * BUFB + doff, Blb + roff);
            }
        }
        CP_COMMIT();

        // ---- compute current stage ----
        const uint32_t aH = s0 + stg * STAGEB;
        const uint32_t bH = aH + 2 * BUFB;
#pragma unroll
        for (int ks = 0; ks < 2; ++ks) {
            const int kc = ks * 16;
            uint32_t ah[4][4], al[4][4];
            uint32_t bh[4][2], bl[4][2];
#pragma unroll
            for (int i = 0; i < 4; ++i) {
                uint32_t addr = aH + (uint32_t)((wm * 64 + i * 16 + (lane & 15)) * ROWB
                                 + kc * 2 + (lane >> 4) * 16);
                LDSM4(ah[i], addr);
                LDSM4(al[i], addr + BUFB);
            }
#pragma unroll
            for (int jj = 0; jj < 2; ++jj) {
                uint32_t addr = bH + (uint32_t)((wn * 32 + jj * 16 + (lane & 15)) * ROWB
                                 + kc * 2 + (lane >> 4) * 16);
                uint32_t t[4];
                LDSM4(t, addr);
                bh[2 * jj][0] = t[0]; bh[2 * jj][1] = t[2];
                bh[2 * jj + 1][0] = t[1]; bh[2 * jj + 1][1] = t[3];
                LDSM4(t, addr + BUFB);
                bl[2 * jj][0] = t[0]; bl[2 * jj][1] = t[2];
                bl[2 * jj + 1][0] = t[1]; bl[2 * jj + 1][1] = t[3];
            }
#pragma unroll
            for (int i = 0; i < 4; ++i) {
#pragma unroll
                for (int j = 0; j < 4; ++j) {
                    MMA_BF16(acc[i][j], ah[i], bh[j][0], bh[j][1]);
                    MMA_BF16(acc[i][j], ah[i], bl[j][0], bl[j][1]);
                    MMA_BF16(acc[i][j], al[i], bh[j][0], bh[j][1]);
                }
            }
        }
        stg = (stg + 1 == STAGES) ? 0 : stg + 1;
    }

    // ---- epilogue: bias + store fp32 ----
#pragma unroll
    for (int i = 0; i < 4; ++i) {
        const int row = bm0 + wm * 64 + i * 16 + (lane >> 2);
#pragma unroll
        for (int j = 0; j < 4; ++j) {
            const int col = bn0 + wn * 32 + j * 8 + (lane & 3) * 2;
            const float b0 = bias[col], b1 = bias[col + 1];
            float2 v0 = make_float2(acc[i][j][0] + b0, acc[i][j][1] + b1);
            float2 v1 = make_float2(acc[i][j][2] + b0, acc[i][j][3] + b1);
            *reinterpret_cast<float2*>(C + (size_t)row * N + col) = v0;
            *reinterpret_cast<float2*>(C + (size_t)(row + 8) * N + col) = v1;
        }
    }
}

// ======================================================================
// Partial RoPE on q (cols [0,2560)) and k (cols [2560,5120)) of g_qkv.
// ======================================================================
__global__ __launch_bounds__(256) void rope_kernel(
    float* __restrict__ qkv, const float* __restrict__ cosb,
    const float* __restrict__ sinb)
{
    const int t = blockIdx.x;
    float* row = qkv + (size_t)t * QKVD;
    for (int w = threadIdx.x; w < 64 * RHALF; w += blockDim.x) {
        int head = w / RHALF;
        int i    = w % RHALF;
        int base = head * HD;
        float c = cosb[t * RHALF + i];
        float s = sinb[t * RHALF + i];
        float x1 = row[base + i];
        float x2 = row[base + RHALF + i];
        row[base + i]          = x1 * c - x2 * s;
        row[base + RHALF + i]  = x2 * c + x1 * s;
    }
}

// ======================================================================
// Flash attention (fp32, causal) — unchanged from R1 (passing, ~1.6ms).
// ======================================================================
#define QT 64
#define KT 64
#define QKP 68
#define VP  84

struct FlashSmem {
    float Qs[HD][QKP];
    float Ks[HD][QKP];
    float Vs[KT][VP];
    float Ss[QT][KT + 1];
};

__global__ __launch_bounds__(256) void flash_kernel(
    const float* __restrict__ qkv, float* __restrict__ attn_out)
{
    extern __shared__ char smem_raw[];
    FlashSmem& sm = *reinterpret_cast<FlashSmem*>(smem_raw);

    const int qt = blockIdx.x;
    const int h  = blockIdx.y;
    const int b  = blockIdx.z;
    const int tid = threadIdx.x;

    const int tc = tid & 15;
    const int tr = tid >> 4;
    const int orow = tid >> 2;
    const int og   = tid & 3;

    const int tq0 = b * SEQ + qt * QT;

    for (int idx = tid; idx < QT * (HD / 4); idx += 256) {
        int r  = idx / (HD / 4);
        int d4 = (idx % (HD / 4)) * 4;
        float4 qv = *reinterpret_cast<const float4*>(
            qkv + (size_t)(tq0 + r) * QKVD + h * HD + d4);
        sm.Qs[d4 + 0][r] = qv.x; sm.Qs[d4 + 1][r] = qv.y;
        sm.Qs[d4 + 2][r] = qv.z; sm.Qs[d4 + 3][r] = qv.w;
    }

    float m = -1e30f;
    float lsum = 0.f;
    float O[20];
#pragma unroll
    for (int d = 0; d < 20; d++) O[d] = 0.f;

    for (int kt = 0; kt <= qt; kt++) {
        const int tk0 = b * SEQ + kt * KT;

        for (int idx = tid; idx < KT * (HD / 4); idx += 256) {
            int r  = idx / (HD / 4);
            int d4 = (idx % (HD / 4)) * 4;
            const float* base = qkv + (size_t)(tk0 + r) * QKVD + h * HD + d4;
            float4 kv = *reinterpret_cast<const float4*>(base + HID);
            sm.Ks[d4 + 0][r] = kv.x; sm.Ks[d4 + 1][r] = kv.y;
            sm.Ks[d4 + 2][r] = kv.z; sm.Ks[d4 + 3][r] = kv.w;
            float4 vv = *reinterpret_cast<const float4*>(base + 2 * HID);
            *reinterpret_cast<float4*>(&sm.Vs[r][d4]) = vv;
        }
        __syncthreads();

        {
            float acc[4][4];
#pragma unroll
            for (int i = 0; i < 4; i++)
#pragma unroll
                for (int j = 0; j < 4; j++) acc[i][j] = 0.f;

            for (int d = 0; d < HD; d++) {
                float4 q4 = *reinterpret_cast<const float4*>(&sm.Qs[d][tr * 4]);
                float4 k4 = *reinterpret_cast<const float4*>(&sm.Ks[d][tc * 4]);
                float qa[4] = {q4.x, q4.y, q4.z, q4.w};
                float ka[4] = {k4.x, k4.y, k4.z, k4.w};
#pragma unroll
                for (int i = 0; i < 4; i++)
#pragma unroll
                    for (int j = 0; j < 4; j++)
                        acc[i][j] = fmaf(qa[i], ka[j], acc[i][j]);
            }
#pragma unroll
            for (int i = 0; i < 4; i++)
#pragma unroll
                for (int j = 0; j < 4; j++)
                    sm.Ss[tr * 4 + i][tc * 4 + j] = acc[i][j] * ATT_SCALE;
        }
        __syncthreads();

        {
            const int c0 = og * 16;
            const bool diag = (kt == qt);
            float sv[16];
            float tmax = -1e30f;
#pragma unroll
            for (int i = 0; i < 16; i++) {
                int c = c0 + i;
                float s = sm.Ss[orow][c];
                if (diag && c > orow) s = -1e30f;
                sv[i] = s;
                tmax = fmaxf(tmax, s);
            }
            tmax = fmaxf(tmax, __shfl_xor_sync(0xffffffffu, tmax, 1));
            tmax = fmaxf(tmax, __shfl_xor_sync(0xffffffffu, tmax, 2));

            float newm = fmaxf(m, tmax);
            float alpha = __expf(m - newm);
            float lpart = 0.f;
#pragma unroll
            for (int i = 0; i < 16; i++) {
                float p = __expf(sv[i] - newm);
                sm.Ss[orow][c0 + i] = p;
                lpart += p;
            }
            lsum = lsum * alpha + lpart;
            m = newm;
#pragma unroll
            for (int d = 0; d < 20; d++) O[d] *= alpha;
        }
        __syncwarp();

        {
            const int d0 = og * 20;
            for (int j = 0; j < KT; j++) {
                float p = sm.Ss[orow][j];
                const float* vrow = &sm.Vs[j][d0];
#pragma unroll
                for (int c = 0; c < 5; c++) {
                    float4 v4 = *reinterpret_cast<const float4*>(vrow + c * 4);
                    O[c * 4 + 0] = fmaf(p, v4.x, O[c * 4 + 0]);
                    O[c * 4 + 1] = fmaf(p, v4.y, O[c * 4 + 1]);
                    O[c * 4 + 2] = fmaf(p, v4.z, O[c * 4 + 2]);
                    O[c * 4 + 3] = fmaf(p, v4.w, O[c * 4 + 3]);
                }
            }
        }
        __syncthreads();
    }

    float ltot = lsum;
    ltot += __shfl_xor_sync(0xffffffffu, ltot, 1);
    ltot += __shfl_xor_sync(0xffffffffu, ltot, 2);
    float inv = 1.f / ltot;

    const int t = tq0 + orow;
    float* dst = attn_out + (size_t)t * HID + h * HD + og * 20;
#pragma unroll
    for (int d = 0; d < 20; d++) dst[d] = O[d] * inv;
}

// ======================================================================
// launch
// ======================================================================
extern "C" void kernel_launch(void* const* d_in, const int* in_sizes, int n_in,
                              void* d_out, int out_size)
{
    const float* hidden  = (const float*)d_in[0];
    const float* cosb    = (const float*)d_in[1];
    const float* sinb    = (const float*)d_in[2];
    const float* w_qkv   = (const float*)d_in[3];
    const float* b_qkv   = (const float*)d_in[4];
    const float* w_dense = (const float*)d_in[5];
    const float* b_dense = (const float*)d_in[6];
    float* out = (float*)d_out;

    float *qkv = nullptr, *attn = nullptr;
    __nv_bfloat16 *ah = nullptr, *al = nullptr, *wh = nullptr, *wl = nullptr;
    cudaGetSymbolAddress((void**)&qkv, g_qkv);
    cudaGetSymbolAddress((void**)&attn, g_attn);
    cudaGetSymbolAddress((void**)&ah, g_ah);
    cudaGetSymbolAddress((void**)&al, g_al);
    cudaGetSymbolAddress((void**)&wh, g_wh);
    cudaGetSymbolAddress((void**)&wl, g_wl);

    cudaFuncSetAttribute(gemm_bf16_split,
                         cudaFuncAttributeMaxDynamicSharedMemorySize, GSMEM);
    cudaFuncSetAttribute(flash_kernel,
                         cudaFuncAttributeMaxDynamicSharedMemorySize,
                         (int)sizeof(FlashSmem));

    const int nA4 = TKN * HID / 4;      // 5,242,880
    const int nW4 = QKVD * HID / 4;     // 4,915,200
    const int nD4 = HID * HID / 4;      // 1,638,400

    // 1) split hidden + w_qkv to bf16 hi/lo
    split_kernel<<<(nA4 + 255) / 256, 256>>>(
        (const float4*)hidden, (uint2*)ah, (uint2*)al, nA4);
    split_kernel<<<(nW4 + 255) / 256, 256>>>(
        (const float4*)w_qkv, (uint2*)wh, (uint2*)wl, nW4);

    // 2) QKV projection: [8192,2560] @ [7680,2560]^T + b -> [8192,7680]
    gemm_bf16_split<<<dim3(QKVD / BN, TKN / BM), 256, GSMEM>>>(
        ah, al, wh, wl, b_qkv, qkv, TKN, QKVD, HID);

    // 3) partial RoPE in place on q,k
    rope_kernel<<<TKN, 256>>>(qkv, cosb, sinb);

    // 4) causal flash attention -> g_attn [8192,2560]
    flash_kernel<<<dim3(SEQ / QT, NH, BATCH), 256, sizeof(FlashSmem)>>>(qkv, attn);

    // 5) split attn + w_dense
    split_kernel<<<(nA4 + 255) / 256, 256>>>(
        (const float4*)attn, (uint2*)ah, (uint2*)al, nA4);
    split_kernel<<<(nD4 + 255) / 256, 256>>>(
        (const float4*)w_dense, (uint2*)wh, (uint2*)wl, nD4);

    // 6) dense projection: [8192,2560] @ [2560,2560]^T + b -> out
    gemm_bf16_split<<<dim3(HID / BN, TKN / BM), 256, GSMEM>>>(
        ah, al, wh, wl, b_dense, out, TKN, HID, HID);
}